// round 1
// baseline (speedup 1.0000x reference)
#include <cuda_runtime.h>

#define BB 128
#define NN 512
#define DD 300
#define AA 32

// Scratch: Q row-major [B*N, A]; K transposed per batch [B][A][N]
__device__ float g_Q[BB * NN * AA];
__device__ float g_Kt[BB * AA * NN];

// ---------------------------------------------------------------------------
// Kernel 1: Q|K projection. GEMM [65536, 300] @ [300, 64].
// Block tile: 256 rows x 64 cols, k-chunks of 8. 256 threads, 8x8 micro-tile.
// ---------------------------------------------------------------------------
__global__ __launch_bounds__(256, 1) void qk_kernel(
    const float* __restrict__ X,
    const float* __restrict__ Wq,
    const float* __restrict__ Wk)
{
    __shared__ float Xs[256 * 9];   // 256 rows x 8 k, stride 9 (pad)
    __shared__ float Ws[8 * 68];    // 8 k x 64 cols, stride 68

    const int tid = threadIdx.x;
    const int row0 = blockIdx.x * 256;
    const int rg = tid >> 3;        // 0..31 -> rows rg*8..rg*8+7
    const int cg = tid & 7;         // 0..7  -> cols cg*8..cg*8+7

    float acc[8][8];
#pragma unroll
    for (int i = 0; i < 8; i++)
#pragma unroll
        for (int j = 0; j < 8; j++) acc[i][j] = 0.0f;

    for (int k0 = 0; k0 < DD; k0 += 8) {
        // --- stage X tile: thread t loads row row0+t, cols k0..k0+7 ---
        {
            const float* xr = X + (long)(row0 + tid) * DD + k0;
            float* xs = &Xs[tid * 9];
            if (k0 + 8 <= DD) {
                float4 v0 = *(const float4*)(xr);
                float4 v1 = *(const float4*)(xr + 4);
                xs[0] = v0.x; xs[1] = v0.y; xs[2] = v0.z; xs[3] = v0.w;
                xs[4] = v1.x; xs[5] = v1.y; xs[6] = v1.z; xs[7] = v1.w;
            } else {
#pragma unroll
                for (int kk = 0; kk < 8; kk++)
                    xs[kk] = (k0 + kk < DD) ? xr[kk] : 0.0f;
            }
        }
        // --- stage W tile: Wq | Wk concat, 8 x 64 ---
        for (int idx = tid; idx < 512; idx += 256) {
            int kk = idx >> 6, a = idx & 63;
            float v = 0.0f;
            if (k0 + kk < DD)
                v = (a < 32) ? Wq[(k0 + kk) * AA + a] : Wk[(k0 + kk) * AA + (a - 32)];
            Ws[kk * 68 + a] = v;
        }
        __syncthreads();

#pragma unroll
        for (int k = 0; k < 8; k++) {
            float a[8], b[8];
#pragma unroll
            for (int i = 0; i < 8; i++) a[i] = Xs[(rg * 8 + i) * 9 + k];
            float4 b0 = *(const float4*)&Ws[k * 68 + cg * 8];
            float4 b1 = *(const float4*)&Ws[k * 68 + cg * 8 + 4];
            b[0] = b0.x; b[1] = b0.y; b[2] = b0.z; b[3] = b0.w;
            b[4] = b1.x; b[5] = b1.y; b[6] = b1.z; b[7] = b1.w;
#pragma unroll
            for (int i = 0; i < 8; i++)
#pragma unroll
                for (int j = 0; j < 8; j++) acc[i][j] += a[i] * b[j];
        }
        __syncthreads();
    }

    // store: cols 0..31 -> Q (row-major), cols 32..63 -> Kt (transposed per batch)
#pragma unroll
    for (int i = 0; i < 8; i++) {
        const int row = row0 + rg * 8 + i;     // global row = b*512 + n
        const int b = row >> 9;
        const int n = row & 511;
#pragma unroll
        for (int j = 0; j < 8; j++) {
            const int c = cg * 8 + j;
            if (c < 32) g_Q[row * AA + c] = acc[i][j];
            else        g_Kt[b * (AA * NN) + (c - 32) * NN + n] = acc[i][j];
        }
    }
}

// ---------------------------------------------------------------------------
// Kernel 2: fused scores + adj-weighting + softmax + attn@X.
// One block = one batch b, 64 query rows. 256 threads.
// smem (dynamic, 204800 B):
//   Ps  [64][512]  scores/probs          32768 floats
//   KXs            Kst[32][512] (phase1) then Xs[32 rows][304] (phase3)
//                                        16384 floats
//   Qs  [64][32]                          2048 floats
// ---------------------------------------------------------------------------
#define SM_PS   0
#define SM_KX   (64 * 512)
#define SM_QS   (64 * 512 + 32 * 512)
#define SM_WORDS (64 * 512 + 32 * 512 + 64 * 32)

__global__ __launch_bounds__(256, 1) void attn_kernel(
    const float* __restrict__ X,
    const float* __restrict__ adj,
    float* __restrict__ out)
{
    extern __shared__ float sm[];
    float* Ps  = sm + SM_PS;
    float* KXs = sm + SM_KX;
    float* Qs  = sm + SM_QS;

    const int tid = threadIdx.x;
    const int b = blockIdx.x >> 3;
    const int row0 = (blockIdx.x & 7) * 64;

    // ---- stage Kst[k][m] (already transposed in gmem) and Qs ----
    {
        const float4* gk4 = (const float4*)(g_Kt + b * (AA * NN));
        float4* ks4 = (float4*)KXs;
        for (int idx = tid; idx < (AA * NN) / 4; idx += 256)
            ks4[idx] = gk4[idx];
        const float4* gq4 = (const float4*)(g_Q + (b * NN + row0) * AA);
        float4* qs4 = (float4*)Qs;
        for (int idx = tid; idx < (64 * AA) / 4; idx += 256)
            qs4[idx] = gq4[idx];
    }
    __syncthreads();

    // ---- Phase 1: scores = (Q K^T) * adj ----
    {
        const int tx = tid & 31;      // m-lane
        const int ty = tid >> 5;      // 0..7 -> rows ty*8..ty*8+7
#pragma unroll
        for (int pp = 0; pp < 2; pp++) {
            const int rl0 = ty * 8 + pp * 4;
            float acc[4][16];
#pragma unroll
            for (int i = 0; i < 4; i++)
#pragma unroll
                for (int jm = 0; jm < 16; jm++) acc[i][jm] = 0.0f;

            for (int k = 0; k < AA; k++) {
                float q[4];
#pragma unroll
                for (int i = 0; i < 4; i++) q[i] = Qs[(rl0 + i) * AA + k];
                const float* Krow = &KXs[k * NN + tx];
#pragma unroll
                for (int jm = 0; jm < 16; jm++) {
                    float kv = Krow[32 * jm];
#pragma unroll
                    for (int i = 0; i < 4; i++) acc[i][jm] += q[i] * kv;
                }
            }
#pragma unroll
            for (int i = 0; i < 4; i++) {
                const int rglob = b * NN + row0 + rl0 + i;
                const float* arow = adj + (long)rglob * NN;
#pragma unroll
                for (int jm = 0; jm < 16; jm++) {
                    const int m = tx + 32 * jm;
                    Ps[(rl0 + i) * NN + m] = acc[i][jm] * arow[m];
                }
            }
        }
    }
    __syncthreads();

    // ---- Phase 2: row softmax over m (512) ----
    {
        const int lane = tid & 31;
        const int w = tid >> 5;
        for (int r = w * 8; r < w * 8 + 8; r++) {
            float* pr = Ps + r * NN;
            float v[16];
            float mx = -1e30f;
#pragma unroll
            for (int j = 0; j < 16; j++) {
                v[j] = pr[lane + 32 * j];
                mx = fmaxf(mx, v[j]);
            }
#pragma unroll
            for (int o = 16; o > 0; o >>= 1)
                mx = fmaxf(mx, __shfl_xor_sync(0xffffffffu, mx, o));
            float s = 0.0f;
#pragma unroll
            for (int j = 0; j < 16; j++) {
                v[j] = expf(v[j] - mx);
                s += v[j];
            }
#pragma unroll
            for (int o = 16; o > 0; o >>= 1)
                s += __shfl_xor_sync(0xffffffffu, s, o);
            const float inv = 1.0f / s;
#pragma unroll
            for (int j = 0; j < 16; j++)
                pr[lane + 32 * j] = v[j] * inv;
        }
    }
    __syncthreads();

    // ---- Phase 3: out[64,300] = P[64,512] @ X[b][512,300] ----
    {
        const int cg = tid & 31;      // col lane: cols cg + 32*j, j=0..9
        const int rg = tid >> 5;      // 0..7 -> rows rg*8..rg*8+7
        float* Xs = KXs;              // reuse: 32 rows x stride 304
        float acc[8][10];
#pragma unroll
        for (int i = 0; i < 8; i++)
#pragma unroll
            for (int j = 0; j < 10; j++) acc[i][j] = 0.0f;

        for (int mc = 0; mc < 16; mc++) {
            const int m0 = mc * 32;
            // stage 32 X rows (75 float4 per row)
            for (int idx = tid; idx < 32 * 75; idx += 256) {
                const int mm = idx / 75;
                const int c4 = idx % 75;
                float4 v = *(const float4*)(X + (long)(b * NN + m0 + mm) * DD + c4 * 4);
                *(float4*)(Xs + mm * 304 + c4 * 4) = v;
            }
            __syncthreads();
#pragma unroll 4
            for (int mm = 0; mm < 32; mm++) {
                float pv[8], xv[10];
#pragma unroll
                for (int i = 0; i < 8; i++) pv[i] = Ps[(rg * 8 + i) * NN + m0 + mm];
#pragma unroll
                for (int j = 0; j < 10; j++) xv[j] = Xs[mm * 304 + cg + 32 * j];
#pragma unroll
                for (int i = 0; i < 8; i++)
#pragma unroll
                    for (int j = 0; j < 10; j++) acc[i][j] += pv[i] * xv[j];
            }
            __syncthreads();
        }

#pragma unroll
        for (int i = 0; i < 8; i++) {
            const long rglob = (long)(b * NN + row0 + rg * 8 + i);
#pragma unroll
            for (int j = 0; j < 10; j++) {
                const int c = cg + 32 * j;
                if (c < DD) out[rglob * DD + c] = acc[i][j];
            }
        }
    }
}

// ---------------------------------------------------------------------------
extern "C" void kernel_launch(void* const* d_in, const int* in_sizes, int n_in,
                              void* d_out, int out_size)
{
    const float* X   = (const float*)d_in[0];  // node_reprs [B,N,D]
    const float* adj = (const float*)d_in[1];  // adjacency  [B,N,N]
    const float* Wq  = (const float*)d_in[2];  // [D,A]
    const float* Wk  = (const float*)d_in[3];  // [D,A]
    float* out = (float*)d_out;                // [B,N,D]

    cudaFuncSetAttribute(attn_kernel, cudaFuncAttributeMaxDynamicSharedMemorySize,
                         SM_WORDS * sizeof(float));

    qk_kernel<<<(BB * NN) / 256, 256>>>(X, Wq, Wk);
    attn_kernel<<<BB * 8, 256, SM_WORDS * sizeof(float)>>>(X, adj, out);
}

// round 2
// speedup vs baseline: 1.2761x; 1.2761x over previous
#include <cuda_runtime.h>

#define BB 128
#define NN 512
#define DD 300
#define AA 32

typedef unsigned long long ull;

// packed f32x2 helpers (sm_103a)
__device__ __forceinline__ void fma2(ull& d, ull a, ull b) {
    asm("fma.rn.f32x2 %0, %1, %2, %0;" : "+l"(d) : "l"(a), "l"(b));
}
__device__ __forceinline__ ull mul2(ull a, ull b) {
    ull r; asm("mul.rn.f32x2 %0, %1, %2;" : "=l"(r) : "l"(a), "l"(b)); return r;
}
__device__ __forceinline__ ull dup2(float x) {
    ull r; asm("mov.b64 %0, {%1, %1};" : "=l"(r) : "f"(x)); return r;
}
__device__ __forceinline__ void unpack2(ull v, float& lo, float& hi) {
    asm("mov.b64 {%0, %1}, %2;" : "=f"(lo), "=f"(hi) : "l"(v));
}

// Scratch: Q row-major [B*N, A]; K transposed per batch [B][A][N]
__device__ float g_Q[BB * NN * AA];
__device__ float g_Kt[BB * AA * NN];

// ---------------------------------------------------------------------------
// Kernel 1: Q|K projection. GEMM [65536, 300] @ [300, 64].
// 256 rows x 64 cols per block, 8x8 micro-tile via f32x2 pairs.
// ---------------------------------------------------------------------------
__global__ __launch_bounds__(256, 1) void qk_kernel(
    const float* __restrict__ X,
    const float* __restrict__ Wq,
    const float* __restrict__ Wk)
{
    __shared__ float Xs[256 * 9];
    __shared__ float Ws[8 * 68];

    const int tid = threadIdx.x;
    const int row0 = blockIdx.x * 256;
    const int rg = tid >> 3;
    const int cg = tid & 7;

    ull acc[8][4];
#pragma unroll
    for (int i = 0; i < 8; i++)
#pragma unroll
        for (int j = 0; j < 4; j++) acc[i][j] = 0ull;

    for (int k0 = 0; k0 < DD; k0 += 8) {
        {
            const float* xr = X + (long)(row0 + tid) * DD + k0;
            float* xs = &Xs[tid * 9];
            if (k0 + 8 <= DD) {
                float4 v0 = *(const float4*)(xr);
                float4 v1 = *(const float4*)(xr + 4);
                xs[0] = v0.x; xs[1] = v0.y; xs[2] = v0.z; xs[3] = v0.w;
                xs[4] = v1.x; xs[5] = v1.y; xs[6] = v1.z; xs[7] = v1.w;
            } else {
#pragma unroll
                for (int kk = 0; kk < 8; kk++)
                    xs[kk] = (k0 + kk < DD) ? xr[kk] : 0.0f;
            }
        }
        for (int idx = tid; idx < 512; idx += 256) {
            int kk = idx >> 6, a = idx & 63;
            float v = 0.0f;
            if (k0 + kk < DD)
                v = (a < 32) ? Wq[(k0 + kk) * AA + a] : Wk[(k0 + kk) * AA + (a - 32)];
            Ws[kk * 68 + a] = v;
        }
        __syncthreads();

#pragma unroll
        for (int k = 0; k < 8; k++) {
            ull ad[8];
#pragma unroll
            for (int i = 0; i < 8; i++) ad[i] = dup2(Xs[(rg * 8 + i) * 9 + k]);
            ull bv[4];
#pragma unroll
            for (int j = 0; j < 4; j++)
                bv[j] = *(const ull*)&Ws[k * 68 + cg * 8 + 2 * j];
#pragma unroll
            for (int i = 0; i < 8; i++)
#pragma unroll
                for (int j = 0; j < 4; j++) fma2(acc[i][j], bv[j], ad[i]);
        }
        __syncthreads();
    }

#pragma unroll
    for (int i = 0; i < 8; i++) {
        const int row = row0 + rg * 8 + i;
        const int b = row >> 9;
        const int n = row & 511;
#pragma unroll
        for (int j = 0; j < 4; j++) {
            const int c = cg * 8 + 2 * j;
            float lo, hi; unpack2(acc[i][j], lo, hi);
            if (c < 32) {
                *(ull*)&g_Q[row * AA + c] = acc[i][j];
            } else {
                g_Kt[b * (AA * NN) + (c - 32) * NN + n] = lo;
                g_Kt[b * (AA * NN) + (c - 31) * NN + n] = hi;
            }
        }
    }
}

// ---------------------------------------------------------------------------
// Kernel 2: fused scores + adj-weighting + softmax + attn@X. 256 threads.
// smem: Ps[64][512] | KXs (Kst[32][512] then Xs[32][304]) | Qs[64][32]
// ---------------------------------------------------------------------------
#define SM_PS   0
#define SM_KX   (64 * 512)
#define SM_QS   (64 * 512 + 32 * 512)
#define SM_WORDS (64 * 512 + 32 * 512 + 64 * 32)

__global__ __launch_bounds__(256, 1) void attn_kernel(
    const float* __restrict__ X,
    const float* __restrict__ adj,
    float* __restrict__ out)
{
    extern __shared__ float sm[];
    float* Ps  = sm + SM_PS;
    float* KXs = sm + SM_KX;
    float* Qs  = sm + SM_QS;

    const int tid = threadIdx.x;
    const int b = blockIdx.x >> 3;
    const int row0 = (blockIdx.x & 7) * 64;

    // ---- stage Kst[k][m] and Qs ----
    {
        const float4* gk4 = (const float4*)(g_Kt + b * (AA * NN));
        float4* ks4 = (float4*)KXs;
        for (int idx = tid; idx < (AA * NN) / 4; idx += 256)
            ks4[idx] = gk4[idx];
        const float4* gq4 = (const float4*)(g_Q + (b * NN + row0) * AA);
        float4* qs4 = (float4*)Qs;
        for (int idx = tid; idx < (64 * AA) / 4; idx += 256)
            qs4[idx] = gq4[idx];
    }
    __syncthreads();

    // ---- Phase 1: scores = (Q K^T) * adj, f32x2 over m-pairs ----
    {
        const int tx = tid & 31;
        const int ty = tid >> 5;
#pragma unroll
        for (int pp = 0; pp < 2; pp++) {
            const int rl0 = ty * 8 + pp * 4;
            ull acc[4][8];
#pragma unroll
            for (int i = 0; i < 4; i++)
#pragma unroll
                for (int jm = 0; jm < 8; jm++) acc[i][jm] = 0ull;

            for (int k = 0; k < AA; k++) {
                ull qd[4];
#pragma unroll
                for (int i = 0; i < 4; i++) qd[i] = dup2(Qs[(rl0 + i) * AA + k]);
                const float* Krow = &KXs[k * NN + 2 * tx];
#pragma unroll
                for (int jm = 0; jm < 8; jm++) {
                    ull kv = *(const ull*)(Krow + 64 * jm);
#pragma unroll
                    for (int i = 0; i < 4; i++) fma2(acc[i][jm], kv, qd[i]);
                }
            }
#pragma unroll
            for (int i = 0; i < 4; i++) {
                const int rglob = b * NN + row0 + rl0 + i;
                const ull* arow = (const ull*)(adj + (long)rglob * NN) + tx;
#pragma unroll
                for (int jm = 0; jm < 8; jm++) {
                    ull prod = mul2(acc[i][jm], arow[32 * jm]);
                    *(ull*)&Ps[(rl0 + i) * NN + 2 * tx + 64 * jm] = prod;
                }
            }
        }
    }
    __syncthreads();

    // ---- Phase 2: row softmax over m (512) ----
    {
        const int lane = tid & 31;
        const int w = tid >> 5;
        for (int r = w * 8; r < w * 8 + 8; r++) {
            float* pr = Ps + r * NN;
            float v[16];
            float mx = -1e30f;
#pragma unroll
            for (int j = 0; j < 16; j++) {
                v[j] = pr[lane + 32 * j];
                mx = fmaxf(mx, v[j]);
            }
#pragma unroll
            for (int o = 16; o > 0; o >>= 1)
                mx = fmaxf(mx, __shfl_xor_sync(0xffffffffu, mx, o));
            float s = 0.0f;
#pragma unroll
            for (int j = 0; j < 16; j++) {
                v[j] = __expf(v[j] - mx);
                s += v[j];
            }
#pragma unroll
            for (int o = 16; o > 0; o >>= 1)
                s += __shfl_xor_sync(0xffffffffu, s, o);
            const float inv = 1.0f / s;
#pragma unroll
            for (int j = 0; j < 16; j++)
                pr[lane + 32 * j] = v[j] * inv;
        }
    }
    __syncthreads();

    // ---- Phase 3: out[64,300] = P[64,512] @ X[b][512,300]; f32x2 col-pairs,
    //      register-prefetch double buffering of the X chunk ----
    {
        const int cg = tid & 31;
        const int rg = tid >> 5;
        float* Xs = KXs;           // reuse: 32 rows, stride 304

        // prefetch slot geometry (constant across chunks)
        int prow[10], pcol[10]; bool pval[10];
#pragma unroll
        for (int t = 0; t < 10; t++) {
            int idx = tid + t * 256;
            pval[t] = idx < 32 * 75;
            prow[t] = idx / 75;
            pcol[t] = idx % 75;
        }

        ull acc[8][5];
#pragma unroll
        for (int i = 0; i < 8; i++)
#pragma unroll
            for (int j = 0; j < 5; j++) acc[i][j] = 0ull;

        float4 pf[10];
        // preload chunk 0
#pragma unroll
        for (int t = 0; t < 10; t++)
            if (pval[t])
                pf[t] = *(const float4*)(X + (long)(b * NN + prow[t]) * DD + pcol[t] * 4);

        for (int mc = 0; mc < 16; mc++) {
            const int m0 = mc * 32;
            __syncthreads();       // prior chunk's compute done
#pragma unroll
            for (int t = 0; t < 10; t++)
                if (pval[t]) *(float4*)(Xs + prow[t] * 304 + pcol[t] * 4) = pf[t];
            __syncthreads();
            if (mc < 15) {
                const int m1 = m0 + 32;
#pragma unroll
                for (int t = 0; t < 10; t++)
                    if (pval[t])
                        pf[t] = *(const float4*)(X + (long)(b * NN + m1 + prow[t]) * DD + pcol[t] * 4);
            }
#pragma unroll 4
            for (int mm = 0; mm < 32; mm++) {
                ull pd[8];
#pragma unroll
                for (int i = 0; i < 8; i++)
                    pd[i] = dup2(Ps[(rg * 8 + i) * NN + m0 + mm]);
                ull xv[5];
#pragma unroll
                for (int j = 0; j < 5; j++)
                    xv[j] = *(const ull*)&Xs[mm * 304 + 2 * cg + 64 * j];
#pragma unroll
                for (int i = 0; i < 8; i++)
#pragma unroll
                    for (int j = 0; j < 5; j++) fma2(acc[i][j], xv[j], pd[i]);
            }
        }

#pragma unroll
        for (int i = 0; i < 8; i++) {
            const long rglob = (long)(b * NN + row0 + rg * 8 + i);
#pragma unroll
            for (int j = 0; j < 5; j++) {
                const int c = 2 * cg + 64 * j;
                float lo, hi; unpack2(acc[i][j], lo, hi);
                if (c < DD)     out[rglob * DD + c] = lo;
                if (c + 1 < DD) out[rglob * DD + c + 1] = hi;
            }
        }
    }
}

// ---------------------------------------------------------------------------
extern "C" void kernel_launch(void* const* d_in, const int* in_sizes, int n_in,
                              void* d_out, int out_size)
{
    const float* X   = (const float*)d_in[0];
    const float* adj = (const float*)d_in[1];
    const float* Wq  = (const float*)d_in[2];
    const float* Wk  = (const float*)d_in[3];
    float* out = (float*)d_out;

    cudaFuncSetAttribute(attn_kernel, cudaFuncAttributeMaxDynamicSharedMemorySize,
                         SM_WORDS * sizeof(float));

    qk_kernel<<<(BB * NN) / 256, 256>>>(X, Wq, Wk);
    attn_kernel<<<BB * 8, 256, SM_WORDS * sizeof(float)>>>(X, adj, out);
}

// round 3
// speedup vs baseline: 1.4391x; 1.1278x over previous
#include <cuda_runtime.h>

#define BB 128
#define NN 512
#define DD 300
#define AA 32

typedef unsigned long long ull;

// packed f32x2 helpers (sm_103a)
__device__ __forceinline__ void fma2(ull& d, ull a, ull b) {
    asm("fma.rn.f32x2 %0, %1, %2, %0;" : "+l"(d) : "l"(a), "l"(b));
}
__device__ __forceinline__ ull mul2(ull a, ull b) {
    ull r; asm("mul.rn.f32x2 %0, %1, %2;" : "=l"(r) : "l"(a), "l"(b)); return r;
}
__device__ __forceinline__ ull dup2(float x) {
    ull r; asm("mov.b64 %0, {%1, %1};" : "=l"(r) : "f"(x)); return r;
}
__device__ __forceinline__ void unpack2(ull v, float& lo, float& hi) {
    asm("mov.b64 {%0, %1}, %2;" : "=f"(lo), "=f"(hi) : "l"(v));
}

// Scratch: Q row-major [B*N, A]; K transposed per batch [B][A][N]
__device__ float g_Q[BB * NN * AA];
__device__ float g_Kt[BB * AA * NN];

// ---------------------------------------------------------------------------
// Kernel 1: Q|K projection. GEMM [65536, 300] @ [300, 64].
// 256 rows x 64 cols per block, 8x8 micro-tile via f32x2, register
// double-buffered staging so LDG overlaps compute.
// ---------------------------------------------------------------------------
__global__ __launch_bounds__(256) void qk_kernel(
    const float* __restrict__ X,
    const float* __restrict__ Wq,
    const float* __restrict__ Wk)
{
    __shared__ float Xs[256 * 9];
    __shared__ float Ws[8 * 68];

    const int tid = threadIdx.x;
    const int row0 = blockIdx.x * 256;
    const int rg = tid >> 3;
    const int cg = tid & 7;

    ull acc[8][4];
#pragma unroll
    for (int i = 0; i < 8; i++)
#pragma unroll
        for (int j = 0; j < 4; j++) acc[i][j] = 0ull;

    // prefetch registers
    float xf[8];
    float wf[2];
    const float* xrow = X + (long)(row0 + tid) * DD;

    // W prefetch geometry: idx0 = tid, idx1 = tid + 256
    const int wk0 = tid >> 6,  wa0 = tid & 63;
    const int wk1 = (tid + 256) >> 6, wa1 = (tid + 256) & 63;

    auto prefetch = [&](int k0) {
        if (k0 + 8 <= DD) {
            float4 v0 = *(const float4*)(xrow + k0);
            float4 v1 = *(const float4*)(xrow + k0 + 4);
            xf[0] = v0.x; xf[1] = v0.y; xf[2] = v0.z; xf[3] = v0.w;
            xf[4] = v1.x; xf[5] = v1.y; xf[6] = v1.z; xf[7] = v1.w;
        } else {
#pragma unroll
            for (int kk = 0; kk < 8; kk++)
                xf[kk] = (k0 + kk < DD) ? xrow[k0 + kk] : 0.0f;
        }
        wf[0] = (k0 + wk0 < DD)
              ? ((wa0 < 32) ? Wq[(k0 + wk0) * AA + wa0] : Wk[(k0 + wk0) * AA + wa0 - 32])
              : 0.0f;
        wf[1] = (k0 + wk1 < DD)
              ? ((wa1 < 32) ? Wq[(k0 + wk1) * AA + wa1] : Wk[(k0 + wk1) * AA + wa1 - 32])
              : 0.0f;
    };

    prefetch(0);

    for (int k0 = 0; k0 < DD; k0 += 8) {
        // write staged regs
        {
            float* xs = &Xs[tid * 9];
#pragma unroll
            for (int kk = 0; kk < 8; kk++) xs[kk] = xf[kk];
            Ws[wk0 * 68 + wa0] = wf[0];
            Ws[wk1 * 68 + wa1] = wf[1];
        }
        __syncthreads();
        if (k0 + 8 < DD) prefetch(k0 + 8);

#pragma unroll
        for (int k = 0; k < 8; k++) {
            ull ad[8];
#pragma unroll
            for (int i = 0; i < 8; i++) ad[i] = dup2(Xs[(rg * 8 + i) * 9 + k]);
            ull bv[4];
#pragma unroll
            for (int j = 0; j < 4; j++)
                bv[j] = *(const ull*)&Ws[k * 68 + cg * 8 + 2 * j];
#pragma unroll
            for (int i = 0; i < 8; i++)
#pragma unroll
                for (int j = 0; j < 4; j++) fma2(acc[i][j], bv[j], ad[i]);
        }
        __syncthreads();
    }

#pragma unroll
    for (int i = 0; i < 8; i++) {
        const int row = row0 + rg * 8 + i;
        const int b = row >> 9;
        const int n = row & 511;
#pragma unroll
        for (int j = 0; j < 4; j++) {
            const int c = cg * 8 + 2 * j;
            float lo, hi; unpack2(acc[i][j], lo, hi);
            if (c < 32) {
                *(ull*)&g_Q[row * AA + c] = acc[i][j];
            } else {
                g_Kt[b * (AA * NN) + (c - 32) * NN + n] = lo;
                g_Kt[b * (AA * NN) + (c - 31) * NN + n] = hi;
            }
        }
    }
}

// ---------------------------------------------------------------------------
// Kernel 2: fused scores + adj-weighting + softmax + attn@X. 512 threads.
// smem: Ps[64][512] | KXs (Kst[32][512] then Xs[32][304]) | Qs[64][32]
// ---------------------------------------------------------------------------
#define SM_PS   0
#define SM_KX   (64 * 512)
#define SM_QS   (64 * 512 + 32 * 512)
#define SM_WORDS (64 * 512 + 32 * 512 + 64 * 32)

__global__ __launch_bounds__(512, 1) void attn_kernel(
    const float* __restrict__ X,
    const float* __restrict__ adj,
    float* __restrict__ out)
{
    extern __shared__ float sm[];
    float* Ps  = sm + SM_PS;
    float* KXs = sm + SM_KX;
    float* Qs  = sm + SM_QS;

    const int tid = threadIdx.x;
    const int b = blockIdx.x >> 3;
    const int row0 = (blockIdx.x & 7) * 64;

    // ---- stage Kst[k][m] and Qs ----
    {
        const float4* gk4 = (const float4*)(g_Kt + b * (AA * NN));
        float4* ks4 = (float4*)KXs;
        for (int idx = tid; idx < (AA * NN) / 4; idx += 512)
            ks4[idx] = gk4[idx];
        const float4* gq4 = (const float4*)(g_Q + (b * NN + row0) * AA);
        float4* qs4 = (float4*)Qs;
        for (int idx = tid; idx < (64 * AA) / 4; idx += 512)
            qs4[idx] = gq4[idx];
    }
    __syncthreads();

    // ---- Phase 1: scores = (Q K^T) * adj; 4 rows x 16 m-pairs / thread ----
    {
        const int tx = tid & 31;       // m-pair lane
        const int ty = tid >> 5;       // 0..15 -> rows ty*4..ty*4+3
        const int rl0 = ty * 4;
        ull acc[4][8];
#pragma unroll
        for (int i = 0; i < 4; i++)
#pragma unroll
            for (int jm = 0; jm < 8; jm++) acc[i][jm] = 0ull;

        for (int k = 0; k < AA; k++) {
            ull qd[4];
#pragma unroll
            for (int i = 0; i < 4; i++) qd[i] = dup2(Qs[(rl0 + i) * AA + k]);
            const float* Krow = &KXs[k * NN + 2 * tx];
#pragma unroll
            for (int jm = 0; jm < 8; jm++) {
                ull kv = *(const ull*)(Krow + 64 * jm);
#pragma unroll
                for (int i = 0; i < 4; i++) fma2(acc[i][jm], kv, qd[i]);
            }
        }
#pragma unroll
        for (int i = 0; i < 4; i++) {
            const int rglob = b * NN + row0 + rl0 + i;
            const ull* arow = (const ull*)(adj + (long)rglob * NN) + tx;
#pragma unroll
            for (int jm = 0; jm < 8; jm++) {
                ull prod = mul2(acc[i][jm], arow[32 * jm]);
                *(ull*)&Ps[(rl0 + i) * NN + 2 * tx + 64 * jm] = prod;
            }
        }
    }
    __syncthreads();

    // ---- Phase 2: row softmax over m (512); 16 warps x 4 rows ----
    {
        const int lane = tid & 31;
        const int w = tid >> 5;
        for (int r = w * 4; r < w * 4 + 4; r++) {
            float* pr = Ps + r * NN;
            float v[16];
            float mx = -1e30f;
#pragma unroll
            for (int j = 0; j < 16; j++) {
                v[j] = pr[lane + 32 * j];
                mx = fmaxf(mx, v[j]);
            }
#pragma unroll
            for (int o = 16; o > 0; o >>= 1)
                mx = fmaxf(mx, __shfl_xor_sync(0xffffffffu, mx, o));
            float s = 0.0f;
#pragma unroll
            for (int j = 0; j < 16; j++) {
                v[j] = __expf(v[j] - mx);
                s += v[j];
            }
#pragma unroll
            for (int o = 16; o > 0; o >>= 1)
                s += __shfl_xor_sync(0xffffffffu, s, o);
            const float inv = 1.0f / s;
#pragma unroll
            for (int j = 0; j < 16; j++)
                pr[lane + 32 * j] = v[j] * inv;
        }
    }
    __syncthreads();

    // ---- Phase 3: out[64,300] = P[64,512] @ X[b][512,300];
    //      4 rows x 10 cols / thread, register-prefetch double buffering ----
    {
        const int cg = tid & 31;       // col-pair lane
        const int rg = tid >> 5;       // 0..15 -> rows rg*4..rg*4+3
        float* Xs = KXs;               // reuse: 32 rows, stride 304

        int prow[5], pcol[5]; bool pval[5];
#pragma unroll
        for (int t = 0; t < 5; t++) {
            int idx = tid + t * 512;
            pval[t] = idx < 32 * 75;
            prow[t] = idx / 75;
            pcol[t] = idx % 75;
        }

        ull acc[4][5];
#pragma unroll
        for (int i = 0; i < 4; i++)
#pragma unroll
            for (int j = 0; j < 5; j++) acc[i][j] = 0ull;

        float4 pf[5];
#pragma unroll
        for (int t = 0; t < 5; t++)
            if (pval[t])
                pf[t] = *(const float4*)(X + (long)(b * NN + prow[t]) * DD + pcol[t] * 4);

        for (int mc = 0; mc < 16; mc++) {
            const int m0 = mc * 32;
            __syncthreads();
#pragma unroll
            for (int t = 0; t < 5; t++)
                if (pval[t]) *(float4*)(Xs + prow[t] * 304 + pcol[t] * 4) = pf[t];
            __syncthreads();
            if (mc < 15) {
                const int m1 = m0 + 32;
#pragma unroll
                for (int t = 0; t < 5; t++)
                    if (pval[t])
                        pf[t] = *(const float4*)(X + (long)(b * NN + m1 + prow[t]) * DD + pcol[t] * 4);
            }
#pragma unroll 4
            for (int mm = 0; mm < 32; mm++) {
                ull pd[4];
#pragma unroll
                for (int i = 0; i < 4; i++)
                    pd[i] = dup2(Ps[(rg * 4 + i) * NN + m0 + mm]);
                ull xv[5];
#pragma unroll
                for (int j = 0; j < 5; j++)
                    xv[j] = *(const ull*)&Xs[mm * 304 + 2 * cg + 64 * j];
#pragma unroll
                for (int i = 0; i < 4; i++)
#pragma unroll
                    for (int j = 0; j < 5; j++) fma2(acc[i][j], xv[j], pd[i]);
            }
        }

#pragma unroll
        for (int i = 0; i < 4; i++) {
            const long rglob = (long)(b * NN + row0 + rg * 4 + i);
#pragma unroll
            for (int j = 0; j < 5; j++) {
                const int c = 2 * cg + 64 * j;
                float lo, hi; unpack2(acc[i][j], lo, hi);
                if (c < DD)     out[rglob * DD + c] = lo;
                if (c + 1 < DD) out[rglob * DD + c + 1] = hi;
            }
        }
    }
}

// ---------------------------------------------------------------------------
extern "C" void kernel_launch(void* const* d_in, const int* in_sizes, int n_in,
                              void* d_out, int out_size)
{
    const float* X   = (const float*)d_in[0];
    const float* adj = (const float*)d_in[1];
    const float* Wq  = (const float*)d_in[2];
    const float* Wk  = (const float*)d_in[3];
    float* out = (float*)d_out;

    cudaFuncSetAttribute(attn_kernel, cudaFuncAttributeMaxDynamicSharedMemorySize,
                         SM_WORDS * sizeof(float));

    qk_kernel<<<(BB * NN) / 256, 256>>>(X, Wq, Wk);
    attn_kernel<<<BB * 8, 512, SM_WORDS * sizeof(float)>>>(X, adj, out);
}